// round 14
// baseline (speedup 1.0000x reference)
#include <cuda_runtime.h>
#include <cuda_bf16.h>
#include <cuda_fp16.h>
#include <math.h>
#include <float.h>
#include <stdint.h>

// Problem constants
#define BB   64
#define TENC 64
#define HH   1024
#define EE   512
#define VV   32000
#define LAT  128
#define STY  64
#define KCAT 192      // LAT + STY
#define G3   3072     // 3*H
#define XCK  2048     // 2*H
#define NBLK (VV / 256)   // 125 logits blocks
#define NSPK 6            // gates split-K partials (2 gi + 4 gh)

#define APAD 72

typedef __nv_bfloat16 bf;

// ---------------- static device scratch (allocation-free) ----------------
__device__ __align__(256) float g_encwaT[BB * HH * TENC]; // enc@Wa^T transposed [b][k][t]
__device__ __align__(256) float g_h  [BB * HH];           // hidden state fp32
__device__ __align__(256) float g_gp [NSPK * BB * G3];    // gates split-K partials
__device__ __align__(256) float g_xc [BB * XCK];          // fp32 [h|ctx] (for exact argmax)
// top-2 argmax partials per (block, row)
__device__ __align__(256) float g_pv1[NBLK * BB];
__device__ __align__(256) int   g_pi1[NBLK * BB];
__device__ __align__(256) float g_pv2[NBLK * BB];
__device__ __align__(256) int   g_pi2[NBLK * BB];

// weights / activations
__device__ __align__(256) half g_WoutF16T[(size_t)VV * XCK];// W_out^T [V][K] fp16
__device__ __align__(256) half g_Af16[BB * XCK];            // logits A fp16 [h|ctx]
__device__ __align__(256) bf g_XEhi[BB * EE];             // gates A (x part)
__device__ __align__(256) bf g_XElo[BB * EE];
__device__ __align__(256) bf g_XHhi[BB * HH];             // gates A (h part)
__device__ __align__(256) bf g_XHlo[BB * HH];
__device__ __align__(256) bf g_EncHi[BB * TENC * HH];     // encoder outputs
__device__ __align__(256) bf g_EncLo[BB * TENC * HH];
__device__ __align__(256) bf g_WaHi[HH * HH];             // W_a [k][h]
__device__ __align__(256) bf g_WaLo[HH * HH];
__device__ __align__(256) bf g_WihHi[G3 * EE];            // W_ih [n][k]
__device__ __align__(256) bf g_WihLo[G3 * EE];
__device__ __align__(256) bf g_WhhHi[G3 * HH];            // W_hh [n][k]
__device__ __align__(256) bf g_WhhLo[G3 * HH];

// ---------------- PTX helpers ----------------

__device__ __forceinline__ void mma16816(float* c, const unsigned* a, const unsigned* b)
{
    asm volatile(
        "mma.sync.aligned.m16n8k16.row.col.f32.bf16.bf16.f32 "
        "{%0,%1,%2,%3}, {%4,%5,%6,%7}, {%8,%9}, {%0,%1,%2,%3};\n"
        : "+f"(c[0]), "+f"(c[1]), "+f"(c[2]), "+f"(c[3])
        : "r"(a[0]), "r"(a[1]), "r"(a[2]), "r"(a[3]), "r"(b[0]), "r"(b[1]));
}

__device__ __forceinline__ void mma16816h(float* c, const unsigned* a, const unsigned* b)
{
    asm volatile(
        "mma.sync.aligned.m16n8k16.row.col.f32.f16.f16.f32 "
        "{%0,%1,%2,%3}, {%4,%5,%6,%7}, {%8,%9}, {%0,%1,%2,%3};\n"
        : "+f"(c[0]), "+f"(c[1]), "+f"(c[2]), "+f"(c[3])
        : "r"(a[0]), "r"(a[1]), "r"(a[2]), "r"(a[3]), "r"(b[0]), "r"(b[1]));
}

__device__ __forceinline__ void cpasync16(void* sdst, const void* gsrc)
{
    unsigned sa = (unsigned)__cvta_generic_to_shared(sdst);
    asm volatile("cp.async.cg.shared.global [%0], [%1], 16;\n" :: "r"(sa), "l"(gsrc));
}
__device__ __forceinline__ void cpasync16s(unsigned saddr, const void* gsrc)
{
    asm volatile("cp.async.cg.shared.global [%0], [%1], 16;\n" :: "r"(saddr), "l"(gsrc));
}

__device__ __forceinline__ void ldsm4(unsigned& r0, unsigned& r1, unsigned& r2, unsigned& r3,
                                      uint32_t saddr)
{
    asm volatile("ldmatrix.sync.aligned.m8n8.x4.shared.b16 {%0,%1,%2,%3}, [%4];"
                 : "=r"(r0), "=r"(r1), "=r"(r2), "=r"(r3) : "r"(saddr));
}

__device__ __forceinline__ uint32_t smem_u32(const void* p)
{
    uint32_t a;
    asm("{ .reg .u64 t; cvta.to.shared.u64 t, %1; cvt.u32.u64 %0, t; }" : "=r"(a) : "l"(p));
    return a;
}

// top-2 helpers (first-index tiebreak)
__device__ __forceinline__ bool gtpair(float x, int i, float y, int j)
{
    return (x > y) || (x == y && i < j);
}
__device__ __forceinline__ void top2_push(float& v1, int& i1, float& v2, int& i2,
                                          float x, int n)
{
    if (gtpair(x, n, v1, i1)) { v2 = v1; i2 = i1; v1 = x; i1 = n; }
    else if (gtpair(x, n, v2, i2)) { v2 = x; i2 = n; }
}
__device__ __forceinline__ void top2_merge(float& a1, int& ai1, float& a2, int& ai2,
                                           float b1, int bi1, float b2, int bi2)
{
    if (gtpair(b1, bi1, a1, ai1)) {
        float n2; int ni2;
        if (gtpair(a1, ai1, b2, bi2)) { n2 = a1; ni2 = ai1; }
        else                          { n2 = b2; ni2 = bi2; }
        a1 = b1; ai1 = bi1; a2 = n2; ai2 = ni2;
    } else {
        if (gtpair(b1, bi1, a2, ai2)) { a2 = b1; ai2 = bi1; }
    }
}

// ---------------- generic hi/lo warp-MMA path (gates/encwa; k=64, 2-stage) ------

template<int NF> struct Cfg {
    static const int BN = 64 * NF;
    static const int SA = 64 * APAD;
    static const int SW = BN * APAD;
    static const int STAGE = 2 * SA + 2 * SW;
    static const int SMEM = 2 * STAGE * 2;
};

template<int NF>
__device__ __forceinline__ void load_stage_t(
    bf* st,
    const bf* __restrict__ Ahi, const bf* __restrict__ Alo, int lda,
    const bf* __restrict__ Whi, const bf* __restrict__ Wlo, int ldw,
    int k0, int tid)
{
    bf* sAhi = st;
    bf* sAlo = st + Cfg<NF>::SA;
    bf* sWhi = st + 2 * Cfg<NF>::SA;
    bf* sWlo = st + 2 * Cfg<NF>::SA + Cfg<NF>::SW;
#pragma unroll
    for (int i = 0; i < 2; i++) {
        int c = tid + i * 256;
        int r = c >> 3, cc = (c & 7) * 8;
        cpasync16(&sAhi[r * APAD + cc], &Ahi[(size_t)r * lda + k0 + cc]);
        cpasync16(&sAlo[r * APAD + cc], &Alo[(size_t)r * lda + k0 + cc]);
    }
#pragma unroll
    for (int i = 0; i < 2 * NF; i++) {
        int c = tid + i * 256;
        int r = c >> 3, cc = (c & 7) * 8;
        cpasync16(&sWhi[r * APAD + cc], &Whi[(size_t)r * ldw + k0 + cc]);
        cpasync16(&sWlo[r * APAD + cc], &Wlo[(size_t)r * ldw + k0 + cc]);
    }
    asm volatile("cp.async.commit_group;\n");
}

template<int NF>
__device__ __forceinline__ void compute_stage_t(
    uint32_t sbase, int warp, int lane, float acc[4][NF][4])
{
    const uint32_t oAlo = Cfg<NF>::SA * 2;
    const uint32_t oWhi = 2 * Cfg<NF>::SA * 2;
    const uint32_t oWlo = (2 * Cfg<NF>::SA + Cfg<NF>::SW) * 2;
    const uint32_t aoff = ((uint32_t)((lane & 7) + ((lane >> 3) & 1) * 8)) * (APAD * 2)
                        + ((uint32_t)(lane >> 4)) * 16;
    const uint32_t boff = ((uint32_t)((lane & 7) + (lane >> 4) * 8)) * (APAD * 2)
                        + ((uint32_t)((lane >> 3) & 1)) * 16;
    const uint32_t wn = (uint32_t)warp * (8 * NF) * (APAD * 2);

#pragma unroll
    for (int kf = 0; kf < 4; kf++) {
        const uint32_t kb = (uint32_t)kf * 32;
        unsigned bhi[NF][2], blo[NF][2];
#pragma unroll
        for (int np = 0; np < NF / 2; np++) {
            const uint32_t ba = sbase + wn + (uint32_t)np * 16 * (APAD * 2) + boff + kb;
            ldsm4(bhi[2 * np][0], bhi[2 * np][1], bhi[2 * np + 1][0], bhi[2 * np + 1][1],
                  ba + oWhi);
            ldsm4(blo[2 * np][0], blo[2 * np][1], blo[2 * np + 1][0], blo[2 * np + 1][1],
                  ba + oWlo);
        }
#pragma unroll
        for (int mt = 0; mt < 4; mt++) {
            const uint32_t aa = sbase + (uint32_t)mt * 16 * (APAD * 2) + aoff + kb;
            unsigned ahi[4], alo[4];
            ldsm4(ahi[0], ahi[1], ahi[2], ahi[3], aa);
            ldsm4(alo[0], alo[1], alo[2], alo[3], aa + oAlo);
#pragma unroll
            for (int nf = 0; nf < NF; nf++) {
                mma16816(acc[mt][nf], ahi, bhi[nf]);
                mma16816(acc[mt][nf], alo, bhi[nf]);
                mma16816(acc[mt][nf], ahi, blo[nf]);
            }
        }
    }
}

template<int NF>
__device__ __forceinline__ void mainloop_t(
    const bf* Ahi, const bf* Alo, int lda,
    const bf* Whi, const bf* Wlo, int ldw,
    int nchunks, float acc[4][NF][4], bf* sm)
{
    const int tid = threadIdx.x, warp = tid >> 5, lane = tid & 31;
    const uint32_t sb = smem_u32(sm);
#pragma unroll
    for (int mt = 0; mt < 4; mt++)
#pragma unroll
        for (int nf = 0; nf < NF; nf++)
#pragma unroll
            for (int i = 0; i < 4; i++) acc[mt][nf][i] = 0.f;

    load_stage_t<NF>(sm, Ahi, Alo, lda, Whi, Wlo, ldw, 0, tid);

    for (int kc = 0; kc < nchunks; kc++) {
        const uint32_t curb = sb + (uint32_t)(kc & 1) * (Cfg<NF>::STAGE * 2);
        if (kc + 1 < nchunks) {
            bf* nxt = sm + ((kc + 1) & 1) * Cfg<NF>::STAGE;
            load_stage_t<NF>(nxt, Ahi, Alo, lda, Whi, Wlo, ldw, (kc + 1) * 64, tid);
        } else {
            asm volatile("cp.async.commit_group;\n");
        }
        asm volatile("cp.async.wait_group 1;\n");
        __syncthreads();
        compute_stage_t<NF>(curb, warp, lane, acc);
        __syncthreads();
    }
}

// ---------------- GRU gates (split-K=6) ----------------
__global__ __launch_bounds__(256) void gates_mma(void)
{
    extern __shared__ bf smg[];
    const int nt = blockIdx.x;
    const int z = blockIdx.y;
    float acc[4][2][4];
    if (z < 2) {
        const int k0 = z * 256;
        mainloop_t<2>(g_XEhi + k0, g_XElo + k0, EE,
                      g_WihHi + (size_t)nt * 128 * EE + k0,
                      g_WihLo + (size_t)nt * 128 * EE + k0, EE,
                      4, acc, smg);
    } else {
        const int k0 = (z - 2) * 256;
        mainloop_t<2>(g_XHhi + k0, g_XHlo + k0, HH,
                      g_WhhHi + (size_t)nt * 128 * HH + k0,
                      g_WhhLo + (size_t)nt * 128 * HH + k0, HH,
                      4, acc, smg);
    }
    float* C = g_gp + (size_t)z * BB * G3;
    const int tid = threadIdx.x, warp = tid >> 5, lane = tid & 31;
    const int g = lane >> 2, tg = lane & 3;
#pragma unroll
    for (int mt = 0; mt < 4; mt++) {
#pragma unroll
        for (int nf = 0; nf < 2; nf++) {
            const int n = nt * 128 + warp * 16 + nf * 8 + tg * 2;
            const int m0r = mt * 16 + g, m1r = m0r + 8;
            *(float2*)&C[(size_t)m0r * G3 + n] = make_float2(acc[mt][nf][0], acc[mt][nf][1]);
            *(float2*)&C[(size_t)m1r * G3 + n] = make_float2(acc[mt][nf][2], acc[mt][nf][3]);
        }
    }
}

// enc_wa with transposed epilogue: g_encwaT[b][k][t]. grid (8, 64), NF=2.
__global__ __launch_bounds__(256) void encwa_mma(void)
{
    extern __shared__ bf sme[];
    const int n0 = blockIdx.x * 128;
    const int m0g = blockIdx.y * 64;
    float acc[4][2][4];
    mainloop_t<2>(g_EncHi + (size_t)m0g * HH, g_EncLo + (size_t)m0g * HH, HH,
                  g_WaHi + (size_t)n0 * HH, g_WaLo + (size_t)n0 * HH, HH,
                  HH / 64, acc, sme);
    const int tid = threadIdx.x, warp = tid >> 5, lane = tid & 31;
    const int g = lane >> 2, tg = lane & 3;
    const int b = m0g >> 6;
    float* dst = g_encwaT + (size_t)b * HH * TENC;
#pragma unroll
    for (int mt = 0; mt < 4; mt++) {
#pragma unroll
        for (int nf = 0; nf < 2; nf++) {
            const int n = n0 + warp * 16 + nf * 8 + tg * 2;
            const int t0 = (m0g + mt * 16 + g) & 63, t1 = t0 + 8;
            dst[(size_t)n * TENC + t0]       = acc[mt][nf][0];
            dst[(size_t)(n + 1) * TENC + t0] = acc[mt][nf][1];
            dst[(size_t)n * TENC + t1]       = acc[mt][nf][2];
            dst[(size_t)(n + 1) * TENC + t1] = acc[mt][nf][3];
        }
    }
}

// ---------------- logits: fp16, k=64 chunks, 3-stage pipeline, 512 threads ----------------
// m-split warp tiling: warps 0-7 rows 0-31, warps 8-15 rows 32-63; each warp 32 n-cols.
#define LSA    (64 * APAD)               // 4608 elems
#define LSW    (256 * APAD)              // 18432 elems
#define LST    (LSA + LSW)               // 23040 elems = 46080 B
#define LSMEM  (3 * LST * 2)             // 138240 B

__device__ __forceinline__ void lg_load(uint32_t sb, int buf, int k0, int n0, int tid)
{
    const uint32_t st = sb + (uint32_t)buf * (LST * 2);
    {   // A: 64 rows x 8 x 16B chunks = 512, one per thread
        int r = tid >> 3, c = tid & 7;
        cpasync16s(st + r * (APAD * 2) + c * 16, &g_Af16[(size_t)r * XCK + k0 + c * 8]);
    }
#pragma unroll
    for (int i = 0; i < 4; i++) {        // W: 256 rows x 8 chunks = 2048, 4 per thread
        int idx = tid + i * 512;
        int r = idx >> 3, c = idx & 7;
        cpasync16s(st + LSA * 2 + r * (APAD * 2) + c * 16,
                   &g_WoutF16T[(size_t)(n0 + r) * XCK + k0 + c * 8]);
    }
    asm volatile("cp.async.commit_group;\n");
}

__global__ __launch_bounds__(512, 1) void logits_mma(
    const float* __restrict__ bias, float* __restrict__ out, int t, int TD)
{
    extern __shared__ bf sml[];
    const uint32_t sb = smem_u32(sml);
    const int tid = threadIdx.x, warp = tid >> 5, lane = tid & 31;
    const int n0 = blockIdx.x * 256;
    const int half = warp >> 3;          // 0: rows 0-31, 1: rows 32-63
    const int wn8 = warp & 7;            // n-slice within half: cols wn8*32..+32

    float acc[2][4][4];
#pragma unroll
    for (int mt = 0; mt < 2; mt++)
#pragma unroll
        for (int nf = 0; nf < 4; nf++)
#pragma unroll
            for (int i = 0; i < 4; i++) acc[mt][nf][i] = 0.f;

    lg_load(sb, 0, 0, n0, tid);
    lg_load(sb, 1, 64, n0, tid);
    lg_load(sb, 2, 128, n0, tid);

    const uint32_t aoff = ((uint32_t)((lane & 7) + ((lane >> 3) & 1) * 8)) * (APAD * 2)
                        + ((uint32_t)(lane >> 4)) * 16;
    const uint32_t boff = ((uint32_t)((lane & 7) + (lane >> 4) * 8)) * (APAD * 2)
                        + ((uint32_t)((lane >> 3) & 1)) * 16;
    const uint32_t arow0 = (uint32_t)(half * 32) * (APAD * 2);
    const uint32_t wrow0 = (uint32_t)(wn8 * 32) * (APAD * 2);

    for (int c = 0; c < 32; c++) {
        asm volatile("cp.async.wait_group 2;\n");
        __syncthreads();
        const uint32_t base = sb + (uint32_t)(c % 3) * (LST * 2);
#pragma unroll
        for (int kf = 0; kf < 4; kf++) {
            const uint32_t kb = (uint32_t)kf * 32;
            unsigned a[2][4], bw[4][2];
#pragma unroll
            for (int mt = 0; mt < 2; mt++) {
                const uint32_t aa = base + arow0 + (uint32_t)mt * 16 * (APAD * 2) + aoff + kb;
                ldsm4(a[mt][0], a[mt][1], a[mt][2], a[mt][3], aa);
            }
#pragma unroll
            for (int np = 0; np < 2; np++) {
                const uint32_t ba = base + LSA * 2 + wrow0 + (uint32_t)np * 16 * (APAD * 2)
                                  + boff + kb;
                ldsm4(bw[2 * np][0], bw[2 * np][1], bw[2 * np + 1][0], bw[2 * np + 1][1], ba);
            }
#pragma unroll
            for (int mt = 0; mt < 2; mt++)
#pragma unroll
                for (int nf = 0; nf < 4; nf++)
                    mma16816h(acc[mt][nf], a[mt], bw[nf]);
        }
        __syncthreads();
        if (c + 3 < 32) lg_load(sb, (c + 3) % 3, (c + 3) * 64, n0, tid);
        else asm volatile("cp.async.commit_group;\n");
    }

    // epilogue: bias + store + fused per-block TOP-2 partials
    const int g = lane >> 2, tg = lane & 3;
    float v1[4], v2[4]; int i1[4], i2[4];
#pragma unroll
    for (int e = 0; e < 4; e++) {
        v1[e] = -FLT_MAX; i1[e] = 0x7fffffff;
        v2[e] = -FLT_MAX; i2[e] = 0x7fffffff;
    }

#pragma unroll
    for (int mt = 0; mt < 2; mt++) {
#pragma unroll
        for (int nf = 0; nf < 4; nf++) {
            const int n = n0 + wn8 * 32 + nf * 8 + tg * 2;
            const float b0v = bias[n], b1v = bias[n + 1];
            acc[mt][nf][0] += b0v; acc[mt][nf][1] += b1v;
            acc[mt][nf][2] += b0v; acc[mt][nf][3] += b1v;
            const int m0r = half * 32 + mt * 16 + g, m1r = m0r + 8;
            *(float2*)&out[((size_t)m0r * TD + t) * VV + n] =
                make_float2(acc[mt][nf][0], acc[mt][nf][1]);
            *(float2*)&out[((size_t)m1r * TD + t) * VV + n] =
                make_float2(acc[mt][nf][2], acc[mt][nf][3]);
            top2_push(v1[mt * 2],     i1[mt * 2],     v2[mt * 2],     i2[mt * 2],     acc[mt][nf][0], n);
            top2_push(v1[mt * 2],     i1[mt * 2],     v2[mt * 2],     i2[mt * 2],     acc[mt][nf][1], n + 1);
            top2_push(v1[mt * 2 + 1], i1[mt * 2 + 1], v2[mt * 2 + 1], i2[mt * 2 + 1], acc[mt][nf][2], n);
            top2_push(v1[mt * 2 + 1], i1[mt * 2 + 1], v2[mt * 2 + 1], i2[mt * 2 + 1], acc[mt][nf][3], n + 1);
        }
    }
#pragma unroll
    for (int off = 1; off <= 2; off <<= 1) {
#pragma unroll
        for (int e = 0; e < 4; e++) {
            float o1 = __shfl_xor_sync(0xffffffffu, v1[e], off);
            int   oi1 = __shfl_xor_sync(0xffffffffu, i1[e], off);
            float o2 = __shfl_xor_sync(0xffffffffu, v2[e], off);
            int   oi2 = __shfl_xor_sync(0xffffffffu, i2[e], off);
            top2_merge(v1[e], i1[e], v2[e], i2[e], o1, oi1, o2, oi2);
        }
    }
    // smem reduce: warp w writes its 32 rows into slot [w][row]
    float* sv1 = (float*)sml;             // [16][64]
    int*   si1 = (int*)(sv1 + 1024);
    float* sv2 = (float*)(si1 + 1024);
    int*   si2 = (int*)(sv2 + 1024);
    if (tg == 0) {
#pragma unroll
        for (int mt = 0; mt < 2; mt++) {
#pragma unroll
            for (int rr = 0; rr < 2; rr++) {
                const int row = half * 32 + mt * 16 + rr * 8 + g;
                sv1[warp * 64 + row] = v1[mt * 2 + rr];
                si1[warp * 64 + row] = i1[mt * 2 + rr];
                sv2[warp * 64 + row] = v2[mt * 2 + rr];
                si2[warp * 64 + row] = i2[mt * 2 + rr];
            }
        }
    }
    __syncthreads();
    if (tid < 64) {
        const int w0 = (tid < 32) ? 0 : 8;     // warps covering this row half
        float a1 = sv1[w0 * 64 + tid], a2 = sv2[w0 * 64 + tid];
        int ai1 = si1[w0 * 64 + tid], ai2 = si2[w0 * 64 + tid];
#pragma unroll
        for (int w = 1; w < 8; w++) {
            top2_merge(a1, ai1, a2, ai2,
                       sv1[(w0 + w) * 64 + tid], si1[(w0 + w) * 64 + tid],
                       sv2[(w0 + w) * 64 + tid], si2[(w0 + w) * 64 + tid]);
        }
        g_pv1[blockIdx.x * 64 + tid] = a1;
        g_pi1[blockIdx.x * 64 + tid] = ai1;
        g_pv2[blockIdx.x * 64 + tid] = a2;
        g_pi2[blockIdx.x * 64 + tid] = ai2;
    }
}

// ---------------- prep kernels ----------------

__global__ void split_hilo(const float* __restrict__ in,
                           bf* __restrict__ hi, bf* __restrict__ lo, int n)
{
    int idx = blockIdx.x * 256 + threadIdx.x;
    if (idx < n) {
        float x = in[idx];
        bf h = __float2bfloat16_rn(x);
        hi[idx] = h;
        lo[idx] = __float2bfloat16_rn(x - __bfloat162float(h));
    }
}

// W_out [K][V] fp32 -> fp16 transposed [V][K]
__global__ __launch_bounds__(256) void wout_f16(const float* __restrict__ W)
{
    __shared__ float tile[32][33];
    const int v0 = blockIdx.x * 32, k0 = blockIdx.y * 32;
    const int tx = threadIdx.x, ty = threadIdx.y;
#pragma unroll
    for (int i = 0; i < 4; i++)
        tile[ty + i * 8][tx] = W[(size_t)(k0 + ty + i * 8) * VV + v0 + tx];
    __syncthreads();
#pragma unroll
    for (int i = 0; i < 4; i++) {
        const int v = v0 + ty + i * 8;
        const int k = k0 + tx;
        g_WoutF16T[(size_t)v * XCK + k] = __float2half_rn(tile[tx][ty + i * 8]);
    }
}

__global__ __launch_bounds__(256) void init_kernel(
    const float* __restrict__ latent, const int* __restrict__ style,
    const float* __restrict__ style_emb, const float* __restrict__ W_l2h,
    const float* __restrict__ b_l2h, const float* __restrict__ emb)
{
    __shared__ float cat[8][KCAT];
    const int bg = blockIdx.y, tid = threadIdx.x;
    const int j = blockIdx.x * 256 + tid;
    for (int idx = tid; idx < 8 * KCAT; idx += 256) {
        int bb = idx / KCAT, k = idx % KCAT;
        int b = bg * 8 + bb;
        cat[bb][k] = (k < LAT) ? latent[b * LAT + k]
                               : style_emb[style[b] * STY + (k - LAT)];
    }
    __syncthreads();
    float acc[8];
    const float bj = b_l2h[j];
#pragma unroll
    for (int bb = 0; bb < 8; bb++) acc[bb] = bj;
    for (int k = 0; k < KCAT; k++) {
        float w = W_l2h[(size_t)k * HH + j];
#pragma unroll
        for (int bb = 0; bb < 8; bb++) acc[bb] += cat[bb][k] * w;
    }
#pragma unroll
    for (int bb = 0; bb < 8; bb++) {
        const int b = bg * 8 + bb;
        g_h[b * HH + j] = acc[bb];
        bf hi = __float2bfloat16_rn(acc[bb]);
        g_XHhi[b * HH + j] = hi;
        g_XHlo[b * HH + j] = __float2bfloat16_rn(acc[bb] - __bfloat162float(hi));
    }
    if (blockIdx.x == 0) {
        for (int idx = tid; idx < 8 * EE; idx += 256) {
            int bb = idx / EE, i = idx % EE;
            float x = emb[EE + i];                 // BOS token = 1
            bf hi = __float2bfloat16_rn(x);
            g_XEhi[(bg * 8 + bb) * EE + i] = hi;
            g_XElo[(bg * 8 + bb) * EE + i] = __float2bfloat16_rn(x - __bfloat162float(hi));
        }
    }
}

// ---------------- fused per-step middle kernel ----------------
__global__ __launch_bounds__(512) void step_mid(
    const float* __restrict__ b_ih, const float* __restrict__ b_hh,
    const float* __restrict__ enc)
{
    __shared__ float hs[HH];
    __shared__ float at[TENC];
    __shared__ float part[8][TENC];
    __shared__ float sred[2];
    const int b = blockIdx.x, tid = threadIdx.x;

    // Phase 1: GRU combine
#pragma unroll
    for (int j = tid; j < HH; j += 512) {
        float ir = b_ih[j], iz = b_ih[HH + j], inn = b_ih[2 * HH + j];
        float hr = b_hh[j], hz = b_hh[HH + j], hn = b_hh[2 * HH + j];
#pragma unroll
        for (int z = 0; z < 2; z++) {
            const float* P = g_gp + (size_t)z * BB * G3 + (size_t)b * G3;
            ir += P[j]; iz += P[HH + j]; inn += P[2 * HH + j];
        }
#pragma unroll
        for (int z = 2; z < 6; z++) {
            const float* P = g_gp + (size_t)z * BB * G3 + (size_t)b * G3;
            hr += P[j]; hz += P[HH + j]; hn += P[2 * HH + j];
        }
        float r  = 1.f / (1.f + expf(-(ir + hr)));
        float zz = 1.f / (1.f + expf(-(iz + hz)));
        float n  = tanhf(inn + r * hn);
        float hnew = (1.f - zz) * n + zz * g_h[b * HH + j];
        hs[j] = hnew;
        g_h[b * HH + j] = hnew;
        bf hi = __float2bfloat16_rn(hnew);
        bf lo = __float2bfloat16_rn(hnew - __bfloat162float(hi));
        g_XHhi[b * HH + j] = hi;             g_XHlo[b * HH + j] = lo;
        g_xc[(size_t)b * XCK + j] = hnew;
        g_Af16[(size_t)b * XCK + j] = __float2half_rn(hnew);
    }
    __syncthreads();

    // Phase 2: scores (coalesced via encwaT)
    {
        const int t = tid & 63, sl = tid >> 6;
        const float* ew = g_encwaT + (size_t)b * HH * TENC;
        float p = 0.f;
        const int kend = sl * 128 + 128;
#pragma unroll 4
        for (int k = sl * 128; k < kend; k++) p += hs[k] * ew[(size_t)k * TENC + t];
        part[sl][t] = p;
    }
    __syncthreads();
    if (tid < 64) {
        float s = 0.f;
#pragma unroll
        for (int sl = 0; sl < 8; sl++) s += part[sl][tid];
        at[tid] = s;
    }
    __syncthreads();
    if (tid < 32) {
        float m = fmaxf(at[tid], at[tid + 32]);
#pragma unroll
        for (int off = 16; off > 0; off >>= 1)
            m = fmaxf(m, __shfl_xor_sync(0xffffffffu, m, off));
        if (tid == 0) sred[0] = m;
    }
    __syncthreads();
    if (tid < 64) at[tid] = expf(at[tid] - sred[0]);
    __syncthreads();
    if (tid < 32) {
        float s = at[tid] + at[tid + 32];
#pragma unroll
        for (int off = 16; off > 0; off >>= 1)
            s += __shfl_xor_sync(0xffffffffu, s, off);
        if (tid == 0) sred[1] = 1.f / s;
    }
    __syncthreads();
    if (tid < 64) at[tid] *= sred[1];
    __syncthreads();

    // Phase 3: ctx
#pragma unroll
    for (int j = tid; j < HH; j += 512) {
        float c = 0.f;
        const float* eb = enc + (size_t)b * TENC * HH + j;
#pragma unroll 8
        for (int t2 = 0; t2 < TENC; t2++) c += at[t2] * eb[(size_t)t2 * HH];
        g_xc[(size_t)b * XCK + HH + j] = c;
        g_Af16[(size_t)b * XCK + HH + j] = __float2half_rn(c);
    }
}

// Final: top-2 reduce over NBLK blocks, EXACT recompute from fp32 W_out,
// pick true winner, gather embedding. grid = BB, 128 threads.
__global__ __launch_bounds__(128) void argmax_final(
    const float* __restrict__ emb, const float* __restrict__ bias,
    const float* __restrict__ Wout)
{
    __shared__ float sv1[128], sv2[128];
    __shared__ int   si1[128], si2[128];
    __shared__ float dsum[128];
    __shared__ int   stok;
    const int b = blockIdx.x, tid = threadIdx.x;

    float a1 = -FLT_MAX, a2 = -FLT_MAX; int ai1 = 0x7fffffff, ai2 = 0x7fffffff;
    if (tid < NBLK) {
        a1 = g_pv1[tid * 64 + b]; ai1 = g_pi1[tid * 64 + b];
        a2 = g_pv2[tid * 64 + b]; ai2 = g_pi2[tid * 64 + b];
    }
    sv1[tid] = a1; si1[tid] = ai1; sv2[tid] = a2; si2[tid] = ai2;
    __syncthreads();
    for (int sft = 64; sft > 0; sft >>= 1) {
        if (tid < sft) {
            float b1 = sv1[tid + sft], b2 = sv2[tid + sft];
            int bj1 = si1[tid + sft], bj2 = si2[tid + sft];
            float c1 = sv1[tid], c2 = sv2[tid];
            int cj1 = si1[tid], cj2 = si2[tid];
            top2_merge(c1, cj1, c2, cj2, b1, bj1, b2, bj2);
            sv1[tid] = c1; si1[tid] = cj1; sv2[tid] = c2; si2[tid] = cj2;
        }
        __syncthreads();
    }
    const int cand1 = si1[0], cand2 = si2[0];

    // exact recompute: d = xc(fp32) . W_out[:, cand] + bias (fp32 weights, exact)
    {
        const int cand = (tid < 64) ? cand1 : cand2;
        const int l = tid & 63;
        const float* xc = g_xc + (size_t)b * XCK;
        float s = 0.f;
#pragma unroll 8
        for (int k = l; k < XCK; k += 64)
            s += xc[k] * Wout[(size_t)k * VV + cand];
        dsum[tid] = s;
    }
    __syncthreads();
    if (tid == 0) {
        float d1 = bias[cand1], d2 = bias[cand2];
        for (int i = 0; i < 64; i++) { d1 += dsum[i]; d2 += dsum[64 + i]; }
        int tok;
        if (d1 > d2)      tok = cand1;
        else if (d2 > d1) tok = cand2;
        else              tok = (cand1 < cand2) ? cand1 : cand2;
        stok = tok;
    }
    __syncthreads();
    const int tok = stok;
    for (int e = tid; e < EE; e += 128) {
        float x = emb[(size_t)tok * EE + e];
        bf hi = __float2bfloat16_rn(x);
        g_XEhi[b * EE + e] = hi;
        g_XElo[b * EE + e] = __float2bfloat16_rn(x - __bfloat162float(hi));
    }
}

// ---------------- host launcher ----------------
extern "C" void kernel_launch(void* const* d_in, const int* in_sizes, int n_in,
                              void* d_out, int out_size)
{
    int ci = 0;
    const float* latent    = (const float*)d_in[ci++];
    const int*   style     = (const int*)  d_in[ci++];
    const float* enc       = (const float*)d_in[ci++];
    if (ci < n_in && in_sizes[ci] == 1) ci++;           // skip max_length scalar if present
    const float* emb       = (const float*)d_in[ci++];
    const float* style_emb = (const float*)d_in[ci++];
    const float* W_l2h     = (const float*)d_in[ci++];
    const float* b_l2h     = (const float*)d_in[ci++];
    const float* W_ih      = (const float*)d_in[ci++];
    const float* W_hh      = (const float*)d_in[ci++];
    const float* b_ih      = (const float*)d_in[ci++];
    const float* b_hh      = (const float*)d_in[ci++];
    const float* W_a       = (const float*)d_in[ci++];
    const float* W_out     = (const float*)d_in[ci++];
    const float* b_out     = (const float*)d_in[ci++];
    float* out = (float*)d_out;

    const int TD = out_size / (BB * VV);                // decode length (32)

    bf *pEncHi, *pEncLo, *pWaHi, *pWaLo, *pWihHi, *pWihLo, *pWhhHi, *pWhhLo;
    cudaGetSymbolAddress((void**)&pEncHi, g_EncHi);
    cudaGetSymbolAddress((void**)&pEncLo, g_EncLo);
    cudaGetSymbolAddress((void**)&pWaHi, g_WaHi);
    cudaGetSymbolAddress((void**)&pWaLo, g_WaLo);
    cudaGetSymbolAddress((void**)&pWihHi, g_WihHi);
    cudaGetSymbolAddress((void**)&pWihLo, g_WihLo);
    cudaGetSymbolAddress((void**)&pWhhHi, g_WhhHi);
    cudaGetSymbolAddress((void**)&pWhhLo, g_WhhLo);

    cudaFuncSetAttribute(logits_mma, cudaFuncAttributeMaxDynamicSharedMemorySize, LSMEM);
    cudaFuncSetAttribute(gates_mma, cudaFuncAttributeMaxDynamicSharedMemorySize,
                         Cfg<2>::SMEM);
    cudaFuncSetAttribute(encwa_mma, cudaFuncAttributeMaxDynamicSharedMemorySize,
                         Cfg<2>::SMEM);

    // one-time per-launch prep
    wout_f16<<<dim3(VV / 32, XCK / 32), dim3(32, 8)>>>(W_out);
    split_hilo<<<(BB * TENC * HH + 255) / 256, 256>>>(enc, pEncHi, pEncLo, BB * TENC * HH);
    split_hilo<<<(HH * HH + 255) / 256, 256>>>(W_a, pWaHi, pWaLo, HH * HH);
    split_hilo<<<(G3 * EE + 255) / 256, 256>>>(W_ih, pWihHi, pWihLo, G3 * EE);
    split_hilo<<<(G3 * HH + 255) / 256, 256>>>(W_hh, pWhhHi, pWhhLo, G3 * HH);
    init_kernel<<<dim3(4, 8), 256>>>(latent, style, style_emb, W_l2h, b_l2h, emb);
    encwa_mma<<<dim3(HH / 128, (BB * TENC) / 64), 256, Cfg<2>::SMEM>>>();

    for (int t = 0; t < TD; t++) {
        gates_mma<<<dim3(G3 / 128, NSPK), 256, Cfg<2>::SMEM>>>();
        step_mid<<<BB, 512>>>(b_ih, b_hh, enc);
        logits_mma<<<NBLK, 512, LSMEM>>>(b_out, out, t, TD);
        argmax_final<<<BB, 128>>>(emb, b_out, W_out);
    }
}

// round 15
// speedup vs baseline: 1.0057x; 1.0057x over previous
#include <cuda_runtime.h>
#include <cuda_bf16.h>
#include <cuda_fp16.h>
#include <math.h>
#include <float.h>
#include <stdint.h>

// Problem constants
#define BB   64
#define TENC 64
#define HH   1024
#define EE   512
#define VV   32000
#define LAT  128
#define STY  64
#define KCAT 192      // LAT + STY
#define G3   3072     // 3*H
#define XCK  2048     // 2*H
#define NBLK (VV / 256)   // 125 logits blocks
#define NSPK 6            // gates split-K partials (2 gi + 4 gh)

#define APAD 72

typedef __nv_bfloat16 bf;

// ---------------- static device scratch (allocation-free) ----------------
__device__ __align__(256) float g_encwaT[BB * HH * TENC]; // enc@Wa^T transposed [b][k][t]
__device__ __align__(256) float g_h  [BB * HH];           // hidden state fp32
__device__ __align__(256) float g_gp [NSPK * BB * G3];    // gates split-K partials
__device__ __align__(256) float g_xc [BB * XCK];          // fp32 [h|ctx] (for exact argmax)
// top-2 argmax partials per (block, row)
__device__ __align__(256) float g_pv1[NBLK * BB];
__device__ __align__(256) int   g_pi1[NBLK * BB];
__device__ __align__(256) float g_pv2[NBLK * BB];
__device__ __align__(256) int   g_pi2[NBLK * BB];

// weights / activations
__device__ __align__(256) half g_WoutF16T[(size_t)VV * XCK];// W_out^T [V][K] fp16
__device__ __align__(256) half g_Af16[BB * XCK];            // logits A fp16 [h|ctx]
__device__ __align__(256) bf g_XEhi[BB * EE];             // gates A (x part)
__device__ __align__(256) bf g_XElo[BB * EE];
__device__ __align__(256) bf g_XHhi[BB * HH];             // gates A (h part)
__device__ __align__(256) bf g_XHlo[BB * HH];
__device__ __align__(256) bf g_EncHi[BB * TENC * HH];     // encoder outputs
__device__ __align__(256) bf g_EncLo[BB * TENC * HH];
__device__ __align__(256) bf g_WaHi[HH * HH];             // W_a [k][h]
__device__ __align__(256) bf g_WaLo[HH * HH];
__device__ __align__(256) bf g_WihHi[G3 * EE];            // W_ih [n][k]
__device__ __align__(256) bf g_WihLo[G3 * EE];
__device__ __align__(256) bf g_WhhHi[G3 * HH];            // W_hh [n][k]
__device__ __align__(256) bf g_WhhLo[G3 * HH];

// ---------------- PTX helpers ----------------

__device__ __forceinline__ void mma16816(float* c, const unsigned* a, const unsigned* b)
{
    asm volatile(
        "mma.sync.aligned.m16n8k16.row.col.f32.bf16.bf16.f32 "
        "{%0,%1,%2,%3}, {%4,%5,%6,%7}, {%8,%9}, {%0,%1,%2,%3};\n"
        : "+f"(c[0]), "+f"(c[1]), "+f"(c[2]), "+f"(c[3])
        : "r"(a[0]), "r"(a[1]), "r"(a[2]), "r"(a[3]), "r"(b[0]), "r"(b[1]));
}

__device__ __forceinline__ void mma16816h(float* c, const unsigned* a, const unsigned* b)
{
    asm volatile(
        "mma.sync.aligned.m16n8k16.row.col.f32.f16.f16.f32 "
        "{%0,%1,%2,%3}, {%4,%5,%6,%7}, {%8,%9}, {%0,%1,%2,%3};\n"
        : "+f"(c[0]), "+f"(c[1]), "+f"(c[2]), "+f"(c[3])
        : "r"(a[0]), "r"(a[1]), "r"(a[2]), "r"(a[3]), "r"(b[0]), "r"(b[1]));
}

__device__ __forceinline__ void cpasync16(void* sdst, const void* gsrc)
{
    unsigned sa = (unsigned)__cvta_generic_to_shared(sdst);
    asm volatile("cp.async.cg.shared.global [%0], [%1], 16;\n" :: "r"(sa), "l"(gsrc));
}
__device__ __forceinline__ void cpasync16s(unsigned saddr, const void* gsrc)
{
    asm volatile("cp.async.cg.shared.global [%0], [%1], 16;\n" :: "r"(saddr), "l"(gsrc));
}

__device__ __forceinline__ void ldsm4(unsigned& r0, unsigned& r1, unsigned& r2, unsigned& r3,
                                      uint32_t saddr)
{
    asm volatile("ldmatrix.sync.aligned.m8n8.x4.shared.b16 {%0,%1,%2,%3}, [%4];"
                 : "=r"(r0), "=r"(r1), "=r"(r2), "=r"(r3) : "r"(saddr));
}

__device__ __forceinline__ uint32_t smem_u32(const void* p)
{
    uint32_t a;
    asm("{ .reg .u64 t; cvta.to.shared.u64 t, %1; cvt.u32.u64 %0, t; }" : "=r"(a) : "l"(p));
    return a;
}

// top-2 helpers (first-index tiebreak)
__device__ __forceinline__ bool gtpair(float x, int i, float y, int j)
{
    return (x > y) || (x == y && i < j);
}
__device__ __forceinline__ void top2_push(float& v1, int& i1, float& v2, int& i2,
                                          float x, int n)
{
    if (gtpair(x, n, v1, i1)) { v2 = v1; i2 = i1; v1 = x; i1 = n; }
    else if (gtpair(x, n, v2, i2)) { v2 = x; i2 = n; }
}
__device__ __forceinline__ void top2_merge(float& a1, int& ai1, float& a2, int& ai2,
                                           float b1, int bi1, float b2, int bi2)
{
    if (gtpair(b1, bi1, a1, ai1)) {
        float n2; int ni2;
        if (gtpair(a1, ai1, b2, bi2)) { n2 = a1; ni2 = ai1; }
        else                          { n2 = b2; ni2 = bi2; }
        a1 = b1; ai1 = bi1; a2 = n2; ai2 = ni2;
    } else {
        if (gtpair(b1, bi1, a2, ai2)) { a2 = b1; ai2 = bi1; }
    }
}

// ---------------- generic hi/lo warp-MMA path (gates/encwa; k=64, 2-stage) ------

template<int NF> struct Cfg {
    static const int BN = 64 * NF;
    static const int SA = 64 * APAD;
    static const int SW = BN * APAD;
    static const int STAGE = 2 * SA + 2 * SW;
    static const int SMEM = 2 * STAGE * 2;
};

template<int NF>
__device__ __forceinline__ void load_stage_t(
    bf* st,
    const bf* __restrict__ Ahi, const bf* __restrict__ Alo, int lda,
    const bf* __restrict__ Whi, const bf* __restrict__ Wlo, int ldw,
    int k0, int tid)
{
    bf* sAhi = st;
    bf* sAlo = st + Cfg<NF>::SA;
    bf* sWhi = st + 2 * Cfg<NF>::SA;
    bf* sWlo = st + 2 * Cfg<NF>::SA + Cfg<NF>::SW;
#pragma unroll
    for (int i = 0; i < 2; i++) {
        int c = tid + i * 256;
        int r = c >> 3, cc = (c & 7) * 8;
        cpasync16(&sAhi[r * APAD + cc], &Ahi[(size_t)r * lda + k0 + cc]);
        cpasync16(&sAlo[r * APAD + cc], &Alo[(size_t)r * lda + k0 + cc]);
    }
#pragma unroll
    for (int i = 0; i < 2 * NF; i++) {
        int c = tid + i * 256;
        int r = c >> 3, cc = (c & 7) * 8;
        cpasync16(&sWhi[r * APAD + cc], &Whi[(size_t)r * ldw + k0 + cc]);
        cpasync16(&sWlo[r * APAD + cc], &Wlo[(size_t)r * ldw + k0 + cc]);
    }
    asm volatile("cp.async.commit_group;\n");
}

template<int NF>
__device__ __forceinline__ void compute_stage_t(
    uint32_t sbase, int warp, int lane, float acc[4][NF][4])
{
    const uint32_t oAlo = Cfg<NF>::SA * 2;
    const uint32_t oWhi = 2 * Cfg<NF>::SA * 2;
    const uint32_t oWlo = (2 * Cfg<NF>::SA + Cfg<NF>::SW) * 2;
    const uint32_t aoff = ((uint32_t)((lane & 7) + ((lane >> 3) & 1) * 8)) * (APAD * 2)
                        + ((uint32_t)(lane >> 4)) * 16;
    const uint32_t boff = ((uint32_t)((lane & 7) + (lane >> 4) * 8)) * (APAD * 2)
                        + ((uint32_t)((lane >> 3) & 1)) * 16;
    const uint32_t wn = (uint32_t)warp * (8 * NF) * (APAD * 2);

#pragma unroll
    for (int kf = 0; kf < 4; kf++) {
        const uint32_t kb = (uint32_t)kf * 32;
        unsigned bhi[NF][2], blo[NF][2];
#pragma unroll
        for (int np = 0; np < NF / 2; np++) {
            const uint32_t ba = sbase + wn + (uint32_t)np * 16 * (APAD * 2) + boff + kb;
            ldsm4(bhi[2 * np][0], bhi[2 * np][1], bhi[2 * np + 1][0], bhi[2 * np + 1][1],
                  ba + oWhi);
            ldsm4(blo[2 * np][0], blo[2 * np][1], blo[2 * np + 1][0], blo[2 * np + 1][1],
                  ba + oWlo);
        }
#pragma unroll
        for (int mt = 0; mt < 4; mt++) {
            const uint32_t aa = sbase + (uint32_t)mt * 16 * (APAD * 2) + aoff + kb;
            unsigned ahi[4], alo[4];
            ldsm4(ahi[0], ahi[1], ahi[2], ahi[3], aa);
            ldsm4(alo[0], alo[1], alo[2], alo[3], aa + oAlo);
#pragma unroll
            for (int nf = 0; nf < NF; nf++) {
                mma16816(acc[mt][nf], ahi, bhi[nf]);
                mma16816(acc[mt][nf], alo, bhi[nf]);
                mma16816(acc[mt][nf], ahi, blo[nf]);
            }
        }
    }
}

template<int NF>
__device__ __forceinline__ void mainloop_t(
    const bf* Ahi, const bf* Alo, int lda,
    const bf* Whi, const bf* Wlo, int ldw,
    int nchunks, float acc[4][NF][4], bf* sm)
{
    const int tid = threadIdx.x, warp = tid >> 5, lane = tid & 31;
    const uint32_t sb = smem_u32(sm);
#pragma unroll
    for (int mt = 0; mt < 4; mt++)
#pragma unroll
        for (int nf = 0; nf < NF; nf++)
#pragma unroll
            for (int i = 0; i < 4; i++) acc[mt][nf][i] = 0.f;

    load_stage_t<NF>(sm, Ahi, Alo, lda, Whi, Wlo, ldw, 0, tid);

    for (int kc = 0; kc < nchunks; kc++) {
        const uint32_t curb = sb + (uint32_t)(kc & 1) * (Cfg<NF>::STAGE * 2);
        if (kc + 1 < nchunks) {
            bf* nxt = sm + ((kc + 1) & 1) * Cfg<NF>::STAGE;
            load_stage_t<NF>(nxt, Ahi, Alo, lda, Whi, Wlo, ldw, (kc + 1) * 64, tid);
        } else {
            asm volatile("cp.async.commit_group;\n");
        }
        asm volatile("cp.async.wait_group 1;\n");
        __syncthreads();
        compute_stage_t<NF>(curb, warp, lane, acc);
        __syncthreads();
    }
}

// gates work body: z in [0,6). z<2: gi slice of K=512; z>=2: gh slice of K=1024.
__device__ __forceinline__ void gates_body(int nt, int z, bf* smg)
{
    float acc[4][2][4];
    if (z < 2) {
        const int k0 = z * 256;
        mainloop_t<2>(g_XEhi + k0, g_XElo + k0, EE,
                      g_WihHi + (size_t)nt * 128 * EE + k0,
                      g_WihLo + (size_t)nt * 128 * EE + k0, EE,
                      4, acc, smg);
    } else {
        const int k0 = (z - 2) * 256;
        mainloop_t<2>(g_XHhi + k0, g_XHlo + k0, HH,
                      g_WhhHi + (size_t)nt * 128 * HH + k0,
                      g_WhhLo + (size_t)nt * 128 * HH + k0, HH,
                      4, acc, smg);
    }
    float* C = g_gp + (size_t)z * BB * G3;
    const int tid = threadIdx.x, warp = tid >> 5, lane = tid & 31;
    const int g = lane >> 2, tg = lane & 3;
#pragma unroll
    for (int mt = 0; mt < 4; mt++) {
#pragma unroll
        for (int nf = 0; nf < 2; nf++) {
            const int n = nt * 128 + warp * 16 + nf * 8 + tg * 2;
            const int m0r = mt * 16 + g, m1r = m0r + 8;
            *(float2*)&C[(size_t)m0r * G3 + n] = make_float2(acc[mt][nf][0], acc[mt][nf][1]);
            *(float2*)&C[(size_t)m1r * G3 + n] = make_float2(acc[mt][nf][2], acc[mt][nf][3]);
        }
    }
}

// standalone gates kernel: grid (24, nz); z = zbase + blockIdx.y
__global__ __launch_bounds__(256) void gates_mma(int zbase)
{
    extern __shared__ bf smg[];
    gates_body(blockIdx.x, zbase + blockIdx.y, smg);
}

// enc_wa with transposed epilogue: g_encwaT[b][k][t]. grid (8, 64), NF=2.
__global__ __launch_bounds__(256) void encwa_mma(void)
{
    extern __shared__ bf sme[];
    const int n0 = blockIdx.x * 128;
    const int m0g = blockIdx.y * 64;
    float acc[4][2][4];
    mainloop_t<2>(g_EncHi + (size_t)m0g * HH, g_EncLo + (size_t)m0g * HH, HH,
                  g_WaHi + (size_t)n0 * HH, g_WaLo + (size_t)n0 * HH, HH,
                  HH / 64, acc, sme);
    const int tid = threadIdx.x, warp = tid >> 5, lane = tid & 31;
    const int g = lane >> 2, tg = lane & 3;
    const int b = m0g >> 6;
    float* dst = g_encwaT + (size_t)b * HH * TENC;
#pragma unroll
    for (int mt = 0; mt < 4; mt++) {
#pragma unroll
        for (int nf = 0; nf < 2; nf++) {
            const int n = n0 + warp * 16 + nf * 8 + tg * 2;
            const int t0 = (m0g + mt * 16 + g) & 63, t1 = t0 + 8;
            dst[(size_t)n * TENC + t0]       = acc[mt][nf][0];
            dst[(size_t)(n + 1) * TENC + t0] = acc[mt][nf][1];
            dst[(size_t)n * TENC + t1]       = acc[mt][nf][2];
            dst[(size_t)(n + 1) * TENC + t1] = acc[mt][nf][3];
        }
    }
}

// ---------------- fused logits (fp16, k=64, 4-stage) + gh-gates ----------------
// blocks [0,125): logits; blocks [125, 221): gh-gates (z=2..5, nt=0..23).
#define LSA    (64 * APAD)               // 4608 elems
#define LSW    (256 * APAD)              // 18432 elems
#define LST    (LSA + LSW)               // 23040 elems = 46080 B
#define LSMEM  (4 * LST * 2)             // 184320 B (4 stages)

__device__ __forceinline__ void lg_load(uint32_t sb, int buf, int k0, int n0, int tid)
{
    const uint32_t st = sb + (uint32_t)buf * (LST * 2);
#pragma unroll
    for (int i = 0; i < 2; i++) {        // A: 64 rows x 8 x 16B chunks
        int idx = tid + i * 256;
        int r = idx >> 3, c = idx & 7;
        cpasync16s(st + r * (APAD * 2) + c * 16, &g_Af16[(size_t)r * XCK + k0 + c * 8]);
    }
#pragma unroll
    for (int i = 0; i < 8; i++) {        // W: 256 rows x 8 chunks
        int idx = tid + i * 256;
        int r = idx >> 3, c = idx & 7;
        cpasync16s(st + LSA * 2 + r * (APAD * 2) + c * 16,
                   &g_WoutF16T[(size_t)(n0 + r) * XCK + k0 + c * 8]);
    }
    asm volatile("cp.async.commit_group;\n");
}

__global__ __launch_bounds__(256, 1) void logits_gh_mma(
    const float* __restrict__ bias, float* __restrict__ out, int t, int TD)
{
    extern __shared__ bf sml[];

    if (blockIdx.x >= NBLK) {
        // gh-gates path for the NEXT step (uses h just written by step_mid)
        const int gid = blockIdx.x - NBLK;        // 0..95
        gates_body(gid % 24, 2 + gid / 24, sml);
        return;
    }

    const uint32_t sb = smem_u32(sml);
    const int tid = threadIdx.x, warp = tid >> 5, lane = tid & 31;
    const int n0 = blockIdx.x * 256;

    float acc[4][4][4];
#pragma unroll
    for (int mt = 0; mt < 4; mt++)
#pragma unroll
        for (int nf = 0; nf < 4; nf++)
#pragma unroll
            for (int i = 0; i < 4; i++) acc[mt][nf][i] = 0.f;

    lg_load(sb, 0, 0, n0, tid);
    lg_load(sb, 1, 64, n0, tid);
    lg_load(sb, 2, 128, n0, tid);
    lg_load(sb, 3, 192, n0, tid);

    const uint32_t aoff = ((uint32_t)((lane & 7) + ((lane >> 3) & 1) * 8)) * (APAD * 2)
                        + ((uint32_t)(lane >> 4)) * 16;
    const uint32_t boff = ((uint32_t)((lane & 7) + (lane >> 4) * 8)) * (APAD * 2)
                        + ((uint32_t)((lane >> 3) & 1)) * 16;
    const uint32_t wn = (uint32_t)warp * 32 * (APAD * 2);

    for (int c = 0; c < 32; c++) {
        asm volatile("cp.async.wait_group 3;\n");
        __syncthreads();
        const uint32_t base = sb + (uint32_t)(c & 3) * (LST * 2);
#pragma unroll
        for (int kf = 0; kf < 4; kf++) {
            const uint32_t kb = (uint32_t)kf * 32;
            unsigned a[4][4], bw[4][2];
#pragma unroll
            for (int mt = 0; mt < 4; mt++) {
                const uint32_t aa = base + (uint32_t)mt * 16 * (APAD * 2) + aoff + kb;
                ldsm4(a[mt][0], a[mt][1], a[mt][2], a[mt][3], aa);
            }
#pragma unroll
            for (int np = 0; np < 2; np++) {
                const uint32_t ba = base + LSA * 2 + wn + (uint32_t)np * 16 * (APAD * 2)
                                  + boff + kb;
                ldsm4(bw[2 * np][0], bw[2 * np][1], bw[2 * np + 1][0], bw[2 * np + 1][1], ba);
            }
#pragma unroll
            for (int mt = 0; mt < 4; mt++)
#pragma unroll
                for (int nf = 0; nf < 4; nf++)
                    mma16816h(acc[mt][nf], a[mt], bw[nf]);
        }
        __syncthreads();
        if (c + 4 < 32) lg_load(sb, (c + 4) & 3, (c + 4) * 64, n0, tid);
        else asm volatile("cp.async.commit_group;\n");
    }

    // epilogue: bias + store + fused per-block TOP-2 partials
    const int g = lane >> 2, tg = lane & 3;
    float v1[8], v2[8]; int i1[8], i2[8];
#pragma unroll
    for (int e = 0; e < 8; e++) {
        v1[e] = -FLT_MAX; i1[e] = 0x7fffffff;
        v2[e] = -FLT_MAX; i2[e] = 0x7fffffff;
    }

#pragma unroll
    for (int mt = 0; mt < 4; mt++) {
#pragma unroll
        for (int nf = 0; nf < 4; nf++) {
            const int n = n0 + warp * 32 + nf * 8 + tg * 2;
            const float b0v = bias[n], b1v = bias[n + 1];
            acc[mt][nf][0] += b0v; acc[mt][nf][1] += b1v;
            acc[mt][nf][2] += b0v; acc[mt][nf][3] += b1v;
            const int m0r = mt * 16 + g, m1r = m0r + 8;
            *(float2*)&out[((size_t)m0r * TD + t) * VV + n] =
                make_float2(acc[mt][nf][0], acc[mt][nf][1]);
            *(float2*)&out[((size_t)m1r * TD + t) * VV + n] =
                make_float2(acc[mt][nf][2], acc[mt][nf][3]);
            top2_push(v1[mt * 2],     i1[mt * 2],     v2[mt * 2],     i2[mt * 2],     acc[mt][nf][0], n);
            top2_push(v1[mt * 2],     i1[mt * 2],     v2[mt * 2],     i2[mt * 2],     acc[mt][nf][1], n + 1);
            top2_push(v1[mt * 2 + 1], i1[mt * 2 + 1], v2[mt * 2 + 1], i2[mt * 2 + 1], acc[mt][nf][2], n);
            top2_push(v1[mt * 2 + 1], i1[mt * 2 + 1], v2[mt * 2 + 1], i2[mt * 2 + 1], acc[mt][nf][3], n + 1);
        }
    }
#pragma unroll
    for (int off = 1; off <= 2; off <<= 1) {
#pragma unroll
        for (int e = 0; e < 8; e++) {
            float o1 = __shfl_xor_sync(0xffffffffu, v1[e], off);
            int   oi1 = __shfl_xor_sync(0xffffffffu, i1[e], off);
            float o2 = __shfl_xor_sync(0xffffffffu, v2[e], off);
            int   oi2 = __shfl_xor_sync(0xffffffffu, i2[e], off);
            top2_merge(v1[e], i1[e], v2[e], i2[e], o1, oi1, o2, oi2);
        }
    }
    float* sv1 = (float*)sml;             // [8][64]
    int*   si1 = (int*)(sv1 + 512);
    float* sv2 = (float*)(si1 + 512);
    int*   si2 = (int*)(sv2 + 512);
    if (tg == 0) {
#pragma unroll
        for (int mt = 0; mt < 4; mt++) {
#pragma unroll
            for (int rr = 0; rr < 2; rr++) {
                const int row = mt * 16 + rr * 8 + g;
                sv1[warp * 64 + row] = v1[mt * 2 + rr];
                si1[warp * 64 + row] = i1[mt * 2 + rr];
                sv2[warp * 64 + row] = v2[mt * 2 + rr];
                si2[warp * 64 + row] = i2[mt * 2 + rr];
            }
        }
    }
    __syncthreads();
    if (tid < 64) {
        float a1 = sv1[tid], a2 = sv2[tid]; int ai1 = si1[tid], ai2 = si2[tid];
#pragma unroll
        for (int w = 1; w < 8; w++) {
            top2_merge(a1, ai1, a2, ai2,
                       sv1[w * 64 + tid], si1[w * 64 + tid],
                       sv2[w * 64 + tid], si2[w * 64 + tid]);
        }
        g_pv1[blockIdx.x * 64 + tid] = a1;
        g_pi1[blockIdx.x * 64 + tid] = ai1;
        g_pv2[blockIdx.x * 64 + tid] = a2;
        g_pi2[blockIdx.x * 64 + tid] = ai2;
    }
}

// ---------------- prep kernels ----------------

// merged hi/lo split of enc, W_a, W_ih, W_hh (segment table hardcoded)
#define SEG0 (BB * TENC * HH)          // enc      4194304
#define SEG1 (SEG0 + HH * HH)          // + W_a    1048576
#define SEG2 (SEG1 + G3 * EE)          // + W_ih   1572864
#define SEG3 (SEG2 + G3 * HH)          // + W_hh   3145728
__global__ void split_all(const float* __restrict__ enc, const float* __restrict__ Wa,
                          const float* __restrict__ Wih, const float* __restrict__ Whh)
{
    int idx = blockIdx.x * 256 + threadIdx.x;
    if (idx >= SEG3) return;
    const float* src; bf *hi, *lo; int off;
    if (idx < SEG0)      { src = enc; hi = g_EncHi; lo = g_EncLo; off = idx; }
    else if (idx < SEG1) { src = Wa;  hi = g_WaHi;  lo = g_WaLo;  off = idx - SEG0; }
    else if (idx < SEG2) { src = Wih; hi = g_WihHi; lo = g_WihLo; off = idx - SEG1; }
    else                 { src = Whh; hi = g_WhhHi; lo = g_WhhLo; off = idx - SEG2; }
    float x = src[off];
    bf h = __float2bfloat16_rn(x);
    hi[off] = h;
    lo[off] = __float2bfloat16_rn(x - __bfloat162float(h));
}

// W_out [K][V] fp32 -> fp16 transposed [V][K]
__global__ __launch_bounds__(256) void wout_f16(const float* __restrict__ W)
{
    __shared__ float tile[32][33];
    const int v0 = blockIdx.x * 32, k0 = blockIdx.y * 32;
    const int tx = threadIdx.x, ty = threadIdx.y;
#pragma unroll
    for (int i = 0; i < 4; i++)
        tile[ty + i * 8][tx] = W[(size_t)(k0 + ty + i * 8) * VV + v0 + tx];
    __syncthreads();
#pragma unroll
    for (int i = 0; i < 4; i++) {
        const int v = v0 + ty + i * 8;
        const int k = k0 + tx;
        g_WoutF16T[(size_t)v * XCK + k] = __float2half_rn(tile[tx][ty + i * 8]);
    }
}

__global__ __launch_bounds__(256) void init_kernel(
    const float* __restrict__ latent, const int* __restrict__ style,
    const float* __restrict__ style_emb, const float* __restrict__ W_l2h,
    const float* __restrict__ b_l2h, const float* __restrict__ emb)
{
    __shared__ float cat[8][KCAT];
    const int bg = blockIdx.y, tid = threadIdx.x;
    const int j = blockIdx.x * 256 + tid;
    for (int idx = tid; idx < 8 * KCAT; idx += 256) {
        int bb = idx / KCAT, k = idx % KCAT;
        int b = bg * 8 + bb;
        cat[bb][k] = (k < LAT) ? latent[b * LAT + k]
                               : style_emb[style[b] * STY + (k - LAT)];
    }
    __syncthreads();
    float acc[8];
    const float bj = b_l2h[j];
#pragma unroll
    for (int bb = 0; bb < 8; bb++) acc[bb] = bj;
    for (int k = 0; k < KCAT; k++) {
        float w = W_l2h[(size_t)k * HH + j];
#pragma unroll
        for (int bb = 0; bb < 8; bb++) acc[bb] += cat[bb][k] * w;
    }
#pragma unroll
    for (int bb = 0; bb < 8; bb++) {
        const int b = bg * 8 + bb;
        g_h[b * HH + j] = acc[bb];
        bf hi = __float2bfloat16_rn(acc[bb]);
        g_XHhi[b * HH + j] = hi;
        g_XHlo[b * HH + j] = __float2bfloat16_rn(acc[bb] - __bfloat162float(hi));
    }
    if (blockIdx.x == 0) {
        for (int idx = tid; idx < 8 * EE; idx += 256) {
            int bb = idx / EE, i = idx % EE;
            float x = emb[EE + i];                 // BOS token = 1
            bf hi = __float2bfloat16_rn(x);
            g_XEhi[(bg * 8 + bb) * EE + i] = hi;
            g_XElo[(bg * 8 + bb) * EE + i] = __float2bfloat16_rn(x - __bfloat162float(hi));
        }
    }
}

// ---------------- fused per-step middle kernel ----------------
__global__ __launch_bounds__(512) void step_mid(
    const float* __restrict__ b_ih, const float* __restrict__ b_hh,
    const float* __restrict__ enc)
{
    __shared__ float hs[HH];
    __shared__ float at[TENC];
    __shared__ float part[8][TENC];
    __shared__ float sred[2];
    const int b = blockIdx.x, tid = threadIdx.x;

    // Phase 1: GRU combine
#pragma unroll
    for (int j = tid; j < HH; j += 512) {
        float ir = b_ih[j], iz = b_ih[HH + j], inn = b_ih[2 * HH + j];
        float hr = b_hh[j], hz = b_hh[HH + j], hn = b_hh[2 * HH + j];
#pragma unroll
        for (int z = 0; z < 2; z++) {
            const float* P = g_gp + (size_t)z * BB * G3 + (size_t)b * G3;
            ir += P[j]; iz += P[HH + j]; inn += P[2 * HH + j];
        }
#pragma unroll
        for (int z = 2; z < 6; z++) {
            const float* P = g_gp + (size_t)z * BB * G3 + (size_t)b * G3;
            hr += P[j]; hz += P[HH + j]; hn += P[2 * HH + j];
        }
        float r  = 1.f / (1.f + expf(-(ir + hr)));
        float zz = 1.f / (1.f + expf(-(iz + hz)));
        float n  = tanhf(inn + r * hn);
        float hnew = (1.f - zz) * n + zz * g_h[b * HH + j];
        hs[j] = hnew;
        g_h[b * HH + j] = hnew;
        bf hi = __float2bfloat16_rn(hnew);
        bf lo = __float2bfloat16_rn(hnew - __bfloat162float(hi));
        g_XHhi[b * HH + j] = hi;             g_XHlo[b * HH + j] = lo;
        g_xc[(size_t)b * XCK + j] = hnew;
        g_Af16[(size_t)b * XCK + j] = __float2half_rn(hnew);
    }
    __syncthreads();

    // Phase 2: scores (coalesced via encwaT)
    {
        const int t = tid & 63, sl = tid >> 6;
        const float* ew = g_encwaT + (size_t)b * HH * TENC;
        float p = 0.f;
        const int kend = sl * 128 + 128;
#pragma unroll 4
        for (int k = sl * 128; k < kend; k++) p += hs[k] * ew[(size_t)k * TENC + t];
        part[sl][t] = p;
    }
    __syncthreads();
    if (tid < 64) {
        float s = 0.f;
#pragma unroll
        for (int sl = 0; sl < 8; sl++) s += part[sl][tid];
        at[tid] = s;
    }
    __syncthreads();
    if (tid < 32) {
        float m = fmaxf(at[tid], at[tid + 32]);
#pragma unroll
        for (int off = 16; off > 0; off >>= 1)
            m = fmaxf(m, __shfl_xor_sync(0xffffffffu, m, off));
        if (tid == 0) sred[0] = m;
    }
    __syncthreads();
    if (tid < 64) at[tid] = expf(at[tid] - sred[0]);
    __syncthreads();
    if (tid < 32) {
        float s = at[tid] + at[tid + 32];
#pragma unroll
        for (int off = 16; off > 0; off >>= 1)
            s += __shfl_xor_sync(0xffffffffu, s, off);
        if (tid == 0) sred[1] = 1.f / s;
    }
    __syncthreads();
    if (tid < 64) at[tid] *= sred[1];
    __syncthreads();

    // Phase 3: ctx
#pragma unroll
    for (int j = tid; j < HH; j += 512) {
        float c = 0.f;
        const float* eb = enc + (size_t)b * TENC * HH + j;
#pragma unroll 8
        for (int t2 = 0; t2 < TENC; t2++) c += at[t2] * eb[(size_t)t2 * HH];
        g_xc[(size_t)b * XCK + HH + j] = c;
        g_Af16[(size_t)b * XCK + HH + j] = __float2half_rn(c);
    }
}

// Final: top-2 reduce over NBLK blocks, EXACT recompute from fp32 W_out,
// pick true winner, gather embedding. grid = BB, 128 threads.
__global__ __launch_bounds__(128) void argmax_final(
    const float* __restrict__ emb, const float* __restrict__ bias,
    const float* __restrict__ Wout)
{
    __shared__ float sv1[128], sv2[128];
    __shared__ int   si1[128], si2[128];
    __shared__ float dsum[128];
    __shared__ int   stok;
    const int b = blockIdx.x, tid = threadIdx.x;

    float a1 = -FLT_MAX, a2 = -FLT_MAX; int ai1 = 0x7fffffff, ai2 = 0x7fffffff;
    if (tid < NBLK) {
        a1 = g_pv1[tid * 64 + b]; ai1 = g_pi1[tid * 64 + b];
        a2 = g_pv2[tid * 64 + b]; ai2 = g_pi2[tid * 64 + b];
    }
    sv1[tid] = a1; si1[tid] = ai1; sv2[tid] = a2; si2[tid] = ai2;
    __syncthreads();
    for (int sft = 64; sft > 0; sft >>= 1) {
        if (tid < sft) {
            float b1 = sv1[tid + sft], b2 = sv2[tid + sft];
            int bj1 = si1[tid + sft], bj2 = si2[tid + sft];
            float c1 = sv1[tid], c2 = sv2[tid];
            int cj1 = si1[tid], cj2 = si2[tid];
            top2_merge(c1, cj1, c2, cj2, b1, bj1, b2, bj2);
            sv1[tid] = c1; si1[tid] = cj1; sv2[tid] = c2; si2[tid] = cj2;
        }
        __syncthreads();
    }
    const int cand1 = si1[0], cand2 = si2[0];

    // exact recompute: d = xc(fp32) . W_out[:, cand] + bias (fp32 weights, exact)
    {
        const int cand = (tid < 64) ? cand1 : cand2;
        const int l = tid & 63;
        const float* xc = g_xc + (size_t)b * XCK;
        float s = 0.f;
#pragma unroll 8
        for (int k = l; k < XCK; k += 64)
            s += xc[k] * Wout[(size_t)k * VV + cand];
        dsum[tid] = s;
    }
    __syncthreads();
    if (tid == 0) {
        float d1 = bias[cand1], d2 = bias[cand2];
        for (int i = 0; i < 64; i++) { d1 += dsum[i]; d2 += dsum[64 + i]; }
        int tok;
        if (d1 > d2)      tok = cand1;
        else if (d2 > d1) tok = cand2;
        else              tok = (cand1 < cand2) ? cand1 : cand2;
        stok = tok;
    }
    __syncthreads();
    const int tok = stok;
    for (int e = tid; e < EE; e += 128) {
        float x = emb[(size_t)tok * EE + e];
        bf hi = __float2bfloat16_rn(x);
        g_XEhi[b * EE + e] = hi;
        g_XElo[b * EE + e] = __float2bfloat16_rn(x - __bfloat162float(hi));
    }
}

// ---------------- host launcher ----------------
extern "C" void kernel_launch(void* const* d_in, const int* in_sizes, int n_in,
                              void* d_out, int out_size)
{
    int ci = 0;
    const float* latent    = (const float*)d_in[ci++];
    const int*   style     = (const int*)  d_in[ci++];
    const float* enc       = (const float*)d_in[ci++];
    if (ci < n_in && in_sizes[ci] == 1) ci++;           // skip max_length scalar if present
    const float* emb       = (const float*)d_in[ci++];
    const float* style_emb = (const float*)d_in[ci++];
    const float* W_l2h     = (const float*)d_in[ci++];
    const float* b_l2h     = (const float*)d_in[ci++];
    const float* W_ih      = (const float*)d_in[ci++];
    const float* W_hh      = (const float*)d_in[ci++];
    const float* b_ih      = (const float*)d_in[ci++];
    const float* b_hh      = (const float*)d_in[ci++];
    const float* W_a       = (const float*)d_in[ci++];
    const float* W_out     = (const float*)d_in[ci++];
    const float* b_out     = (const float*)d_in[ci++];
    float* out = (float*)d_out;

    const int TD = out_size / (BB * VV);                // decode length (32)

    cudaFuncSetAttribute(logits_gh_mma, cudaFuncAttributeMaxDynamicSharedMemorySize,
                         LSMEM);
    cudaFuncSetAttribute(gates_mma, cudaFuncAttributeMaxDynamicSharedMemorySize,
                         Cfg<2>::SMEM);
    cudaFuncSetAttribute(encwa_mma, cudaFuncAttributeMaxDynamicSharedMemorySize,
                         Cfg<2>::SMEM);

    // one-time per-launch prep
    wout_f16<<<dim3(VV / 32, XCK / 32), dim3(32, 8)>>>(W_out);
    split_all<<<(SEG3 + 255) / 256, 256>>>(enc, W_a, W_ih, W_hh);
    init_kernel<<<dim3(4, 8), 256>>>(latent, style, style_emb, W_l2h, b_l2h, emb);
    encwa_mma<<<dim3(HH / 128, (BB * TENC) / 64), 256, Cfg<2>::SMEM>>>();
    // gh(0): h(0) . W_hh  (z = 2..5)
    gates_mma<<<dim3(24, 4), 256, Cfg<2>::SMEM>>>(2);

    for (int t = 0; t < TD; t++) {
        // gi(t): x(t) . W_ih  (z = 0..1); gh(t) already computed
        gates_mma<<<dim3(24, 2), 256, Cfg<2>::SMEM>>>(0);
        step_mid<<<BB, 512>>>(b_ih, b_hh, enc);
        // logits(t) fused with gh(t+1) (both depend only on step_mid(t))
        logits_gh_mma<<<NBLK + 96, 256, LSMEM>>>(b_out, out, t, TD);
        argmax_final<<<BB, 128>>>(emb, b_out, W_out);
    }
}